// round 4
// baseline (speedup 1.0000x reference)
#include <cuda_runtime.h>
#include <cuda_bf16.h>
#include <cstdio>

// Problem constants
#define BB 2
#define LL 2048
#define DD 1024
#define HH 16
#define DK 64
#define DV 64
#define MM (BB*LL)          // 4096

// Scratch (static device globals; no allocation allowed)
__device__ float g_qh[BB*HH*LL*DK];   // [b][h][l][d]
__device__ float g_kh[BB*HH*LL*DK];
__device__ float g_vh[BB*HH*LL*DV];
__device__ float g_ctx[MM*DD];        // [b*l][h*dv]
__device__ float g_tmp[MM*DD];        // fc output pre-LN
__device__ float g_rowinv[BB*HH*LL];  // 1/rowsum per attn row

// ---------------------------------------------------------------------------
// Projection GEMM: Y[b][h][l][d] = X[m][:] @ W[:][n],  m=b*L+l, n=h*64+d
// Tiles: BM=128, BN=64, BK=16; 256 threads; 8x4 micro-tile per thread.
// which: 0->g_qh, 1->g_kh, 2->g_vh
// ---------------------------------------------------------------------------
__global__ void __launch_bounds__(256, 2)
proj_kernel(const float* __restrict__ X, const float* __restrict__ W, int which)
{
    float* Y = (which == 0) ? g_qh : (which == 1) ? g_kh : g_vh;
    __shared__ float As[16][128];   // [k][m]
    __shared__ float Bs[16][64];    // [k][n]
    int tid = threadIdx.x;
    int m0 = blockIdx.y * 128;
    int n0 = blockIdx.x * 64;
    int tx = tid & 15;       // n: 16 * 4 = 64
    int ty = tid >> 4;       // m: 16 * 8 = 128
    float acc[8][4];
    #pragma unroll
    for (int i = 0; i < 8; i++)
        #pragma unroll
        for (int j = 0; j < 4; j++) acc[i][j] = 0.f;

    for (int k0 = 0; k0 < DD; k0 += 16) {
        // load A tile 128x16 (512 float4, 2 per thread), store transposed
        #pragma unroll
        for (int i = 0; i < 2; i++) {
            int f = tid * 2 + i;
            int row = f >> 2;
            int kc  = (f & 3) * 4;
            float4 v = *(const float4*)&X[(size_t)(m0 + row) * DD + k0 + kc];
            As[kc + 0][row] = v.x; As[kc + 1][row] = v.y;
            As[kc + 2][row] = v.z; As[kc + 3][row] = v.w;
        }
        // load B tile 16x64 (256 float4, 1 per thread)
        {
            int kr = tid >> 4;
            int nc = (tid & 15) * 4;
            *(float4*)&Bs[kr][nc] = *(const float4*)&W[(size_t)(k0 + kr) * DD + n0 + nc];
        }
        __syncthreads();
        #pragma unroll
        for (int kk = 0; kk < 16; kk++) {
            float a[8], b[4];
            *(float4*)&a[0] = *(const float4*)&As[kk][ty * 8];
            *(float4*)&a[4] = *(const float4*)&As[kk][ty * 8 + 4];
            *(float4*)&b[0] = *(const float4*)&Bs[kk][tx * 4];
            #pragma unroll
            for (int i = 0; i < 8; i++)
                #pragma unroll
                for (int j = 0; j < 4; j++)
                    acc[i][j] += a[i] * b[j];
        }
        __syncthreads();
    }
    // store to head-major layout
    #pragma unroll
    for (int i = 0; i < 8; i++) {
        int m = m0 + ty * 8 + i;
        int b = m >> 11;           // / 2048
        int l = m & 2047;
        #pragma unroll
        for (int j = 0; j < 4; j++) {
            int n = n0 + tx * 4 + j;
            int h = n >> 6;
            int d = n & 63;
            Y[(size_t)(((b * HH) + h) * LL + l) * 64 + d] = acc[i][j];
        }
    }
}

// ---------------------------------------------------------------------------
// FC GEMM with residual: Y[m][n] = X[m][:]@W[:][n] + R[m][n]   (row-major out)
// ---------------------------------------------------------------------------
__global__ void __launch_bounds__(256, 2)
fc_kernel(const float* __restrict__ W, const float* __restrict__ R)
{
    const float* X = g_ctx;
    float* Y = g_tmp;
    __shared__ float As[16][128];
    __shared__ float Bs[16][64];
    int tid = threadIdx.x;
    int m0 = blockIdx.y * 128;
    int n0 = blockIdx.x * 64;
    int tx = tid & 15;
    int ty = tid >> 4;
    float acc[8][4];
    #pragma unroll
    for (int i = 0; i < 8; i++)
        #pragma unroll
        for (int j = 0; j < 4; j++) acc[i][j] = 0.f;

    for (int k0 = 0; k0 < DD; k0 += 16) {
        #pragma unroll
        for (int i = 0; i < 2; i++) {
            int f = tid * 2 + i;
            int row = f >> 2;
            int kc  = (f & 3) * 4;
            float4 v = *(const float4*)&X[(size_t)(m0 + row) * DD + k0 + kc];
            As[kc + 0][row] = v.x; As[kc + 1][row] = v.y;
            As[kc + 2][row] = v.z; As[kc + 3][row] = v.w;
        }
        {
            int kr = tid >> 4;
            int nc = (tid & 15) * 4;
            *(float4*)&Bs[kr][nc] = *(const float4*)&W[(size_t)(k0 + kr) * DD + n0 + nc];
        }
        __syncthreads();
        #pragma unroll
        for (int kk = 0; kk < 16; kk++) {
            float a[8], b[4];
            *(float4*)&a[0] = *(const float4*)&As[kk][ty * 8];
            *(float4*)&a[4] = *(const float4*)&As[kk][ty * 8 + 4];
            *(float4*)&b[0] = *(const float4*)&Bs[kk][tx * 4];
            #pragma unroll
            for (int i = 0; i < 8; i++)
                #pragma unroll
                for (int j = 0; j < 4; j++)
                    acc[i][j] += a[i] * b[j];
        }
        __syncthreads();
    }
    #pragma unroll
    for (int i = 0; i < 8; i++) {
        size_t m = m0 + ty * 8 + i;
        size_t off = m * DD + n0 + tx * 4;
        float4 r = *(const float4*)&R[off];
        float4 o;
        o.x = acc[i][0] + r.x; o.y = acc[i][1] + r.y;
        o.z = acc[i][2] + r.z; o.w = acc[i][3] + r.w;
        *(float4*)&Y[off] = o;
    }
}

// ---------------------------------------------------------------------------
// Fused attention: per block (b, h, q-tile of 64).
// Computes E = exp(Q K^T / 8) (causal), writes unnormalized E to attn gmem,
// accumulates rowsum and O = E @ V; stores O/rowsum to g_ctx, 1/rowsum to
// g_rowinv. Smem: Qt(16K, d-major) | KV(16K) | Es(16K) = 48KB dynamic.
// ---------------------------------------------------------------------------
__global__ void __launch_bounds__(256, 1)
attn_kernel(float* __restrict__ attn, int writeAttn)
{
    extern __shared__ float sm[];
    float* Qt = sm;             // [d][q] : Qt[dd*64 + q]
    float* KV = sm + 4096;      // Kt [d][k], later Vs [k][dv]
    float* Es = sm + 8192;      // [q][k]

    int qt = blockIdx.x;   // q-tile 0..31
    int h  = blockIdx.y;
    int b  = blockIdx.z;
    int q0 = qt * 64;
    int tid = threadIdx.x;
    int tx = tid & 15;          // k / dv, 4 each
    int ty = tid >> 4;          // q, 4 each

    const float* Qg = g_qh + (size_t)((b * HH + h) * LL + q0) * 64;
    const float* Kg = g_kh + (size_t)((b * HH + h) * LL) * 64;
    const float* Vg = g_vh + (size_t)((b * HH + h) * LL) * 64;

    // load Q tile transposed, pre-scaled by 1/sqrt(dk)=1/8
    #pragma unroll
    for (int i = 0; i < 4; i++) {
        int f = i * 256 + tid;          // float4 index, 1024 total
        int row = f >> 4;
        int c4  = (f & 15) * 4;
        float4 v = *(const float4*)&Qg[(size_t)row * 64 + c4];
        Qt[(c4 + 0) * 64 + row] = v.x * 0.125f;
        Qt[(c4 + 1) * 64 + row] = v.y * 0.125f;
        Qt[(c4 + 2) * 64 + row] = v.z * 0.125f;
        Qt[(c4 + 3) * 64 + row] = v.w * 0.125f;
    }

    float accO[4][4];
    #pragma unroll
    for (int i = 0; i < 4; i++)
        #pragma unroll
        for (int j = 0; j < 4; j++) accO[i][j] = 0.f;
    float sum_part[4] = {0.f, 0.f, 0.f, 0.f};

    for (int kt = 0; kt <= qt; kt++) {
        __syncthreads();   // prev PV done reading KV/Es; Qt load done (1st iter)
        // load K tile transposed into KV: Kt[d][k]
        #pragma unroll
        for (int i = 0; i < 4; i++) {
            int f = i * 256 + tid;
            int row = f >> 4;
            int c4  = (f & 15) * 4;
            float4 v = *(const float4*)&Kg[(size_t)(kt * 64 + row) * 64 + c4];
            KV[(c4 + 0) * 64 + row] = v.x;
            KV[(c4 + 1) * 64 + row] = v.y;
            KV[(c4 + 2) * 64 + row] = v.z;
            KV[(c4 + 3) * 64 + row] = v.w;
        }
        __syncthreads();
        // S = Q K^T over d
        float accS[4][4];
        #pragma unroll
        for (int i = 0; i < 4; i++)
            #pragma unroll
            for (int j = 0; j < 4; j++) accS[i][j] = 0.f;
        #pragma unroll 8
        for (int dd = 0; dd < 64; dd++) {
            float4 av = *(const float4*)&Qt[dd * 64 + ty * 4];
            float4 bv = *(const float4*)&KV[dd * 64 + tx * 4];
            float a[4] = {av.x, av.y, av.z, av.w};
            float bq[4] = {bv.x, bv.y, bv.z, bv.w};
            #pragma unroll
            for (int i = 0; i < 4; i++)
                #pragma unroll
                for (int j = 0; j < 4; j++)
                    accS[i][j] += a[i] * bq[j];
        }
        bool diag = (kt == qt);
        #pragma unroll
        for (int i = 0; i < 4; i++) {
            int qg = q0 + ty * 4 + i;
            float e[4];
            #pragma unroll
            for (int j = 0; j < 4; j++) {
                int kg = kt * 64 + tx * 4 + j;
                float val = (!diag || kg <= qg) ? __expf(accS[i][j]) : 0.f;
                e[j] = val;
                sum_part[i] += val;
            }
            float4 ev = make_float4(e[0], e[1], e[2], e[3]);
            *(float4*)&Es[(ty * 4 + i) * 64 + tx * 4] = ev;
            if (writeAttn) {
                size_t base = ((size_t)(b * HH + h) * LL + qg) * LL + kt * 64 + tx * 4;
                *(float4*)&attn[base] = ev;
            }
        }
        __syncthreads();   // Es complete; done reading KV (Kt)
        // load V tile into KV: Vs[k][dv] (row-major copy)
        #pragma unroll
        for (int i = 0; i < 4; i++) {
            int f = i * 256 + tid;
            int row = f >> 4;
            int c4  = (f & 15) * 4;
            *(float4*)&KV[row * 64 + c4] =
                *(const float4*)&Vg[(size_t)(kt * 64 + row) * 64 + c4];
        }
        __syncthreads();
        // O += E @ V
        #pragma unroll 8
        for (int kk = 0; kk < 64; kk++) {
            float4 bv = *(const float4*)&KV[kk * 64 + tx * 4];
            #pragma unroll
            for (int i = 0; i < 4; i++) {
                float a = Es[(ty * 4 + i) * 64 + kk];
                accO[i][0] += a * bv.x;
                accO[i][1] += a * bv.y;
                accO[i][2] += a * bv.z;
                accO[i][3] += a * bv.w;
            }
        }
    }
    __syncthreads();
    // rowsum reduction: reuse Qt region
    float* red = sm;        // [64][16]
    float* rs  = sm + 1024; // [64]
    #pragma unroll
    for (int i = 0; i < 4; i++)
        red[(ty * 4 + i) * 16 + tx] = sum_part[i];
    __syncthreads();
    if (tid < 64) {
        float s = 0.f;
        #pragma unroll
        for (int j = 0; j < 16; j++) s += red[tid * 16 + j];
        float inv = 1.f / s;
        rs[tid] = inv;
        g_rowinv[(size_t)(b * HH + h) * LL + q0 + tid] = inv;
    }
    __syncthreads();
    // write O / rowsum into g_ctx [b*L + q][h*dv]
    #pragma unroll
    for (int i = 0; i < 4; i++) {
        float inv = rs[ty * 4 + i];
        size_t off = ((size_t)(b * LL + q0 + ty * 4 + i)) * DD + h * 64 + tx * 4;
        float4 o;
        o.x = accO[i][0] * inv; o.y = accO[i][1] * inv;
        o.z = accO[i][2] * inv; o.w = accO[i][3] * inv;
        *(float4*)&g_ctx[off] = o;
    }
}

// ---------------------------------------------------------------------------
// Normalize attn rows (causal part) and zero-fill the masked upper triangle.
// One block per attn row (B*H*L = 65536 rows, 2048 cols each).
// Split loops: RMW only where k <= q; pure zero stores beyond (no dead reads).
// ---------------------------------------------------------------------------
__global__ void __launch_bounds__(256)
rescale_kernel(float* __restrict__ attn)
{
    int r = blockIdx.x;          // (b*H + h)*L + q
    int q = r & (LL - 1);
    float inv = g_rowinv[r];
    size_t base = (size_t)r * LL;
    int kend = q + 1;
    for (int k = threadIdx.x; k < kend; k += 256)
        attn[base + k] *= inv;
    // zero-fill masked region, float4 stores from aligned start
    int z0 = (kend + 3) & ~3;
    for (int k = kend + threadIdx.x; k < z0; k += 256)
        attn[base + k] = 0.f;
    float4 zz = make_float4(0.f, 0.f, 0.f, 0.f);
    for (int k = z0 + threadIdx.x * 4; k < LL; k += 256 * 4)
        *(float4*)&attn[base + k] = zz;
}

// ---------------------------------------------------------------------------
// LayerNorm over last dim (1024), eps=1e-6
// ---------------------------------------------------------------------------
__global__ void __launch_bounds__(256)
ln_kernel(const float* __restrict__ gamma, const float* __restrict__ beta,
          float* __restrict__ Y)
{
    __shared__ float sh[256], sh2[256];
    int row = blockIdx.x;
    int tid = threadIdx.x;
    const float* x = g_tmp + (size_t)row * DD;
    float s = 0.f, s2 = 0.f;
    for (int i = tid; i < DD; i += 256) {
        float v = x[i];
        s += v; s2 += v * v;
    }
    sh[tid] = s; sh2[tid] = s2;
    __syncthreads();
    for (int o = 128; o > 0; o >>= 1) {
        if (tid < o) { sh[tid] += sh[tid + o]; sh2[tid] += sh2[tid + o]; }
        __syncthreads();
    }
    float mean = sh[0] * (1.f / DD);
    float var  = sh2[0] * (1.f / DD) - mean * mean;
    float rstd = rsqrtf(var + 1e-6f);
    for (int i = tid; i < DD; i += 256) {
        float v = x[i];
        Y[(size_t)row * DD + i] = (v - mean) * rstd * gamma[i] + beta[i];
    }
}

// ---------------------------------------------------------------------------
extern "C" void kernel_launch(void* const* d_in, const int* in_sizes, int n_in,
                              void* d_out, int out_size)
{
    const float* q     = (const float*)d_in[0];
    const float* k     = (const float*)d_in[1];
    const float* v     = (const float*)d_in[2];
    const float* Wq    = (const float*)d_in[3];
    const float* Wk    = (const float*)d_in[4];
    const float* Wv    = (const float*)d_in[5];
    const float* Wfc   = (const float*)d_in[6];
    const float* gamma = (const float*)d_in[7];
    const float* beta  = (const float*)d_in[8];
    (void)in_sizes; (void)n_in;  // mask (d_in[9]) is a fixed causal tril; not read

    const long OUTE  = (long)MM * DD;          // 4,194,304
    const long ATTNE = (long)BB * HH * LL * LL; // 134,217,728

    float* out_f = (float*)d_out;
    float* outm  = nullptr;
    float* attnp = nullptr;
    long osz = (long)out_size;
    if (osz >= OUTE + ATTNE) { outm = out_f; attnp = out_f + OUTE; }
    else if (osz == ATTNE)   { attnp = out_f; }
    else                     { outm = out_f; }

    dim3 gp(DD / 64, MM / 128);   // (16, 32)

    // Projections
    proj_kernel<<<gp, 256>>>(q, Wq, 0);
    proj_kernel<<<gp, 256>>>(k, Wk, 1);
    proj_kernel<<<gp, 256>>>(v, Wv, 2);

    // Fused attention (unnormalized E to attn, O/rowsum to ctx)
    dim3 ga(LL / 64, HH, BB);     // (32, 16, 2)
    float* attn_target = attnp ? attnp : (float*)d_out; // unused when !writeAttn
    attn_kernel<<<ga, 256, 49152>>>(attnp ? attnp : attn_target, attnp ? 1 : 0);

    // Normalize + zero-fill attn
    if (attnp) rescale_kernel<<<BB * HH * LL, 256>>>(attnp);

    if (outm) {
        fc_kernel<<<gp, 256>>>(Wfc, q);
        ln_kernel<<<MM, 256>>>(gamma, beta, outm);
    }
}

// round 10
// speedup vs baseline: 1.4142x; 1.4142x over previous
#include <cuda_runtime.h>
#include <cuda_bf16.h>
#include <cstdint>

// Problem constants
#define BB 2
#define LL 2048
#define DD 1024
#define HH 16
#define MM (BB*LL)          // 4096

// ---------------- scratch (static device globals; no allocation) ----------
__device__ float g_qh[(size_t)BB*HH*LL*64];   // [b][h][l][d]
__device__ float g_kh[(size_t)BB*HH*LL*64];
__device__ float g_vh[(size_t)BB*HH*LL*64];
__device__ float g_ctx[(size_t)MM*DD];        // [b*l][h*dv]
__device__ float g_tmp[(size_t)MM*DD];        // fc output pre-LN
__device__ float g_rowinv[(size_t)BB*HH*LL];  // 1/rowsum per attn row

// bf16 hi/lo splits
__device__ __align__(16) __nv_bfloat16 g_ah[3][(size_t)MM*DD];
__device__ __align__(16) __nv_bfloat16 g_al[3][(size_t)MM*DD];
__device__ __align__(16) __nv_bfloat16 g_wh[4][(size_t)DD*DD];  // W^T [n][k]
__device__ __align__(16) __nv_bfloat16 g_wl[4][(size_t)DD*DD];

// ---------------- warp-MMA helpers (baseline PTX, sm_80+: valid on sm_103) --
__device__ __forceinline__ uint32_t s2u(const void* p) {
    uint32_t a;
    asm("{ .reg .u64 t; cvta.to.shared.u64 t, %1; cvt.u32.u64 %0, t; }"
        : "=r"(a) : "l"(p));
    return a;
}
__device__ __forceinline__ void ldsm4(uint32_t* r, uint32_t a) {
    asm volatile("ldmatrix.sync.aligned.m8n8.x4.shared.b16 {%0,%1,%2,%3}, [%4];"
        : "=r"(r[0]), "=r"(r[1]), "=r"(r[2]), "=r"(r[3]) : "r"(a));
}
__device__ __forceinline__ void ldsm2(uint32_t* r, uint32_t a) {
    asm volatile("ldmatrix.sync.aligned.m8n8.x2.shared.b16 {%0,%1}, [%2];"
        : "=r"(r[0]), "=r"(r[1]) : "r"(a));
}
__device__ __forceinline__ void mma16816(float* d, const uint32_t* a, const uint32_t* b) {
    asm volatile(
        "mma.sync.aligned.m16n8k16.row.col.f32.bf16.bf16.f32 "
        "{%0,%1,%2,%3}, {%4,%5,%6,%7}, {%8,%9}, {%0,%1,%2,%3};"
        : "+f"(d[0]), "+f"(d[1]), "+f"(d[2]), "+f"(d[3])
        : "r"(a[0]), "r"(a[1]), "r"(a[2]), "r"(a[3]), "r"(b[0]), "r"(b[1]));
}

// ---------------- conversion kernels ----------------
// fp32 -> bf16 hi/lo split, elementwise (float4 / 4 elems per thread)
__global__ void __launch_bounds__(256)
conv_x_kernel(const float* __restrict__ X, int slot, int fromCtx)
{
    const float* src = fromCtx ? g_ctx : X;
    size_t i = ((size_t)blockIdx.x * 256 + threadIdx.x) * 4;
    float4 v = *(const float4*)(src + i);
    __nv_bfloat16 h0 = __float2bfloat16(v.x), h1 = __float2bfloat16(v.y);
    __nv_bfloat16 h2 = __float2bfloat16(v.z), h3 = __float2bfloat16(v.w);
    __nv_bfloat16 l0 = __float2bfloat16(v.x - __bfloat162float(h0));
    __nv_bfloat16 l1 = __float2bfloat16(v.y - __bfloat162float(h1));
    __nv_bfloat16 l2 = __float2bfloat16(v.z - __bfloat162float(h2));
    __nv_bfloat16 l3 = __float2bfloat16(v.w - __bfloat162float(h3));
    uint2 H, L;
    H.x = (uint32_t)__bfloat16_as_ushort(h0) | ((uint32_t)__bfloat16_as_ushort(h1) << 16);
    H.y = (uint32_t)__bfloat16_as_ushort(h2) | ((uint32_t)__bfloat16_as_ushort(h3) << 16);
    L.x = (uint32_t)__bfloat16_as_ushort(l0) | ((uint32_t)__bfloat16_as_ushort(l1) << 16);
    L.y = (uint32_t)__bfloat16_as_ushort(l2) | ((uint32_t)__bfloat16_as_ushort(l3) << 16);
    *(uint2*)&g_ah[slot][i] = H;
    *(uint2*)&g_al[slot][i] = L;
}

// W[k][n] fp32 -> Wt[n][k] bf16 hi/lo (32x32 smem transpose tiles)
__global__ void __launch_bounds__(256)
conv_wt_kernel(const float* __restrict__ W, int slot)
{
    __shared__ float t[32][33];
    int n0 = blockIdx.x * 32, k0 = blockIdx.y * 32;
    int tx = threadIdx.x & 31, ty = threadIdx.x >> 5;
    #pragma unroll
    for (int i = 0; i < 4; i++)
        t[ty + 8 * i][tx] = W[(size_t)(k0 + ty + 8 * i) * DD + n0 + tx];
    __syncthreads();
    #pragma unroll
    for (int i = 0; i < 4; i++) {
        float v = t[tx][ty + 8 * i];           // = W[k0+tx][n0+ty+8i]
        size_t o = (size_t)(n0 + ty + 8 * i) * DD + k0 + tx;
        __nv_bfloat16 h = __float2bfloat16(v);
        g_wh[slot][o] = h;
        g_wl[slot][o] = __float2bfloat16(v - __bfloat162float(h));
    }
}

// ---------------- 3-term bf16 GEMM via mma.sync ----------------
// Y[m][n] = sum_k X[m][k] W[k][n].  X hi/lo: g_ah/g_al[aslot]  [M=4096][1024]
// W^T hi/lo: g_wh/g_wl[wslot]  [N=1024][1024] (K-major rows = col-major B).
// Block: 128x64, 8 warps, each 32x32.  K-chunks of 64, 4 k16 substeps.
// Terms per k16: Ahi*Bhi + Ahi*Blo + Alo*Bhi.
// mode 0..2: store head-major to g_qh/g_kh/g_vh; mode 3: g_tmp = acc + R.
#define AST 144            // smem row stride bytes (64 bf16 + 16B pad)
#define SM_AH 0
#define SM_AL (128*AST)    // 18432
#define SM_BH (2*128*AST)  // 36864
#define SM_BL (2*128*AST + 64*AST)  // 46080
#define GEMM_SMEM (2*128*AST + 2*64*AST)  // 55296

__global__ void __launch_bounds__(256)
gemm3_kernel(int aslot, int wslot, int mode, const float* __restrict__ R)
{
    extern __shared__ char smp[];
    uint32_t sb = s2u(smp);
    int tid = threadIdx.x, wid = tid >> 5, lane = tid & 31;
    int wm = wid >> 1, wn = wid & 1;          // warp tile: rows wm*32, cols wn*32
    int n0 = blockIdx.x * 64, m0 = blockIdx.y * 128;

    const __nv_bfloat16* Ah = g_ah[aslot];
    const __nv_bfloat16* Al = g_al[aslot];
    const __nv_bfloat16* Bh = g_wh[wslot];
    const __nv_bfloat16* Bl = g_wl[wslot];

    float acc[2][4][4];
    #pragma unroll
    for (int mt = 0; mt < 2; mt++)
        #pragma unroll
        for (int nt = 0; nt < 4; nt++)
            #pragma unroll
            for (int j = 0; j < 4; j++) acc[mt][nt][j] = 0.f;

    for (int kt = 0; kt < 16; kt++) {
        int k0 = kt * 64;
        __syncthreads();
        // Load tiles: Ahi(1024 u4) Alo(1024) Bhi(512) Blo(512) = 12 u4/thread
        #pragma unroll
        for (int i = 0; i < 12; i++) {
            int idx = i * 256 + tid;
            if (idx < 1024) {
                int r = idx >> 3, c = idx & 7;
                *(uint4*)(smp + SM_AH + r * AST + c * 16) =
                    *(const uint4*)&Ah[(size_t)(m0 + r) * DD + k0 + c * 8];
            } else if (idx < 2048) {
                int j = idx - 1024; int r = j >> 3, c = j & 7;
                *(uint4*)(smp + SM_AL + r * AST + c * 16) =
                    *(const uint4*)&Al[(size_t)(m0 + r) * DD + k0 + c * 8];
            } else if (idx < 2560) {
                int j = idx - 2048; int r = j >> 3, c = j & 7;
                *(uint4*)(smp + SM_BH + r * AST + c * 16) =
                    *(const uint4*)&Bh[(size_t)(n0 + r) * DD + k0 + c * 8];
            } else {
                int j = idx - 2560; int r = j >> 3, c = j & 7;
                *(uint4*)(smp + SM_BL + r * AST + c * 16) =
                    *(const uint4*)&Bl[(size_t)(n0 + r) * DD + k0 + c * 8];
            }
        }
        __syncthreads();
        #pragma unroll
        for (int s = 0; s < 4; s++) {          // k16 substeps within chunk
            int ks = s * 16;
            uint32_t aH[2][4], aL[2][4], bH[4][2], bL[4][2];
            #pragma unroll
            for (int mt = 0; mt < 2; mt++) {
                uint32_t ra = sb + SM_AH + (wm * 32 + mt * 16 + (lane & 15)) * AST
                            + (ks + (lane >> 4) * 8) * 2;
                ldsm4(aH[mt], ra);
                ldsm4(aL[mt], ra + (SM_AL - SM_AH));
            }
            #pragma unroll
            for (int nt = 0; nt < 4; nt++) {
                uint32_t rb = sb + SM_BH + (wn * 32 + nt * 8 + (lane & 7)) * AST
                            + (ks + ((lane >> 3) & 1) * 8) * 2;
                ldsm2(bH[nt], rb);
                ldsm2(bL[nt], rb + (SM_BL - SM_BH));
            }
            #pragma unroll
            for (int mt = 0; mt < 2; mt++)
                #pragma unroll
                for (int nt = 0; nt < 4; nt++) {
                    mma16816(acc[mt][nt], aH[mt], bH[nt]);
                    mma16816(acc[mt][nt], aH[mt], bL[nt]);
                    mma16816(acc[mt][nt], aL[mt], bH[nt]);
                }
        }
    }
    // Epilogue: d frag mapping: rows lane/4 (+8), cols (lane&3)*2 (+1)
    int r0 = lane >> 2, c0 = (lane & 3) * 2;
    #pragma unroll
    for (int mt = 0; mt < 2; mt++)
        #pragma unroll
        for (int nt = 0; nt < 4; nt++) {
            int cc = wn * 32 + nt * 8 + c0;    // 0..63 within n-block
            #pragma unroll
            for (int half = 0; half < 2; half++) {
                int m = m0 + wm * 32 + mt * 16 + r0 + half * 8;
                float2 dv = make_float2(acc[mt][nt][half * 2 + 0],
                                        acc[mt][nt][half * 2 + 1]);
                if (mode < 3) {
                    float* Y = (mode == 0) ? g_qh : (mode == 1) ? g_kh : g_vh;
                    int b = m >> 11, l = m & 2047, h = n0 >> 6;
                    *(float2*)&Y[((size_t)((b * HH) + h) * LL + l) * 64 + cc] = dv;
                } else {
                    size_t off = (size_t)m * DD + n0 + cc;
                    float2 rr = *(const float2*)&R[off];
                    dv.x += rr.x; dv.y += rr.y;
                    *(float2*)&g_tmp[off] = dv;
                }
            }
        }
}

// ---------------------------------------------------------------------------
// Fused attention (unchanged SIMT fp32): per block (b, h, q-tile of 64).
// ---------------------------------------------------------------------------
__global__ void __launch_bounds__(256, 1)
attn_kernel(float* __restrict__ attn, int writeAttn)
{
    extern __shared__ float sm[];
    float* Qt = sm;             // [d][q]
    float* KV = sm + 4096;      // Kt [d][k], later Vs [k][dv]
    float* Es = sm + 8192;      // [q][k]

    int qt = blockIdx.x;
    int h  = blockIdx.y;
    int b  = blockIdx.z;
    int q0 = qt * 64;
    int tid = threadIdx.x;
    int tx = tid & 15;
    int ty = tid >> 4;

    const float* Qg = g_qh + (size_t)((b * HH + h) * LL + q0) * 64;
    const float* Kg = g_kh + (size_t)((b * HH + h) * LL) * 64;
    const float* Vg = g_vh + (size_t)((b * HH + h) * LL) * 64;

    #pragma unroll
    for (int i = 0; i < 4; i++) {
        int f = i * 256 + tid;
        int row = f >> 4;
        int c4  = (f & 15) * 4;
        float4 v = *(const float4*)&Qg[(size_t)row * 64 + c4];
        Qt[(c4 + 0) * 64 + row] = v.x * 0.125f;
        Qt[(c4 + 1) * 64 + row] = v.y * 0.125f;
        Qt[(c4 + 2) * 64 + row] = v.z * 0.125f;
        Qt[(c4 + 3) * 64 + row] = v.w * 0.125f;
    }

    float accO[4][4];
    #pragma unroll
    for (int i = 0; i < 4; i++)
        #pragma unroll
        for (int j = 0; j < 4; j++) accO[i][j] = 0.f;
    float sum_part[4] = {0.f, 0.f, 0.f, 0.f};

    for (int kt = 0; kt <= qt; kt++) {
        __syncthreads();
        #pragma unroll
        for (int i = 0; i < 4; i++) {
            int f = i * 256 + tid;
            int row = f >> 4;
            int c4  = (f & 15) * 4;
            float4 v = *(const float4*)&Kg[(size_t)(kt * 64 + row) * 64 + c4];
            KV[(c4 + 0) * 64 + row] = v.x;
            KV[(c4 + 1) * 64 + row] = v.y;
            KV[(c4 + 2) * 64 + row] = v.z;
            KV[(c4 + 3) * 64 + row] = v.w;
        }
        __syncthreads();
        float accS[4][4];
        #pragma unroll
        for (int i = 0; i < 4; i++)
            #pragma unroll
            for (int j = 0; j < 4; j++) accS[i][j] = 0.f;
        #pragma unroll 8
        for (int dd = 0; dd < 64; dd++) {
            float4 av = *(const float4*)&Qt[dd * 64 + ty * 4];
            float4 bv = *(const float4*)&KV[dd * 64 + tx * 4];
            float a[4] = {av.x, av.y, av.z, av.w};
            float bq[4] = {bv.x, bv.y, bv.z, bv.w};
            #pragma unroll
            for (int i = 0; i < 4; i++)
                #pragma unroll
                for (int j = 0; j < 4; j++)
                    accS[i][j] += a[i] * bq[j];
        }
        bool diag = (kt == qt);
        #pragma unroll
        for (int i = 0; i < 4; i++) {
            int qg = q0 + ty * 4 + i;
            float e[4];
            #pragma unroll
            for (int j = 0; j < 4; j++) {
                int kg = kt * 64 + tx * 4 + j;
                float val = (!diag || kg <= qg) ? __expf(accS[i][j]) : 0.f;
                e[j] = val;
                sum_part[i] += val;
            }
            float4 ev = make_float4(e[0], e[1], e[2], e[3]);
            *(float4*)&Es[(ty * 4 + i) * 64 + tx * 4] = ev;
            if (writeAttn) {
                size_t base = ((size_t)(b * HH + h) * LL + qg) * LL + kt * 64 + tx * 4;
                *(float4*)&attn[base] = ev;
            }
        }
        __syncthreads();
        #pragma unroll
        for (int i = 0; i < 4; i++) {
            int f = i * 256 + tid;
            int row = f >> 4;
            int c4  = (f & 15) * 4;
            *(float4*)&KV[row * 64 + c4] =
                *(const float4*)&Vg[(size_t)(kt * 64 + row) * 64 + c4];
        }
        __syncthreads();
        #pragma unroll 8
        for (int kk = 0; kk < 64; kk++) {
            float4 bv = *(const float4*)&KV[kk * 64 + tx * 4];
            #pragma unroll
            for (int i = 0; i < 4; i++) {
                float a = Es[(ty * 4 + i) * 64 + kk];
                accO[i][0] += a * bv.x;
                accO[i][1] += a * bv.y;
                accO[i][2] += a * bv.z;
                accO[i][3] += a * bv.w;
            }
        }
    }
    __syncthreads();
    float* red = sm;
    float* rs  = sm + 1024;
    #pragma unroll
    for (int i = 0; i < 4; i++)
        red[(ty * 4 + i) * 16 + tx] = sum_part[i];
    __syncthreads();
    if (tid < 64) {
        float s = 0.f;
        #pragma unroll
        for (int j = 0; j < 16; j++) s += red[tid * 16 + j];
        float inv = 1.f / s;
        rs[tid] = inv;
        g_rowinv[(size_t)(b * HH + h) * LL + q0 + tid] = inv;
    }
    __syncthreads();
    #pragma unroll
    for (int i = 0; i < 4; i++) {
        float inv = rs[ty * 4 + i];
        size_t off = ((size_t)(b * LL + q0 + ty * 4 + i)) * DD + h * 64 + tx * 4;
        float4 o;
        o.x = accO[i][0] * inv; o.y = accO[i][1] * inv;
        o.z = accO[i][2] * inv; o.w = accO[i][3] * inv;
        *(float4*)&g_ctx[off] = o;
    }
}

// ---------------------------------------------------------------------------
__global__ void __launch_bounds__(256)
rescale_kernel(float* __restrict__ attn)
{
    int r = blockIdx.x;
    int q = r & (LL - 1);
    float inv = g_rowinv[r];
    size_t base = (size_t)r * LL;
    int kend = q + 1;
    for (int k = threadIdx.x; k < kend; k += 256)
        attn[base + k] *= inv;
    int z0 = (kend + 3) & ~3;
    for (int k = kend + threadIdx.x; k < z0; k += 256)
        attn[base + k] = 0.f;
    float4 zz = make_float4(0.f, 0.f, 0.f, 0.f);
    for (int k = z0 + threadIdx.x * 4; k < LL; k += 256 * 4)
        *(float4*)&attn[base + k] = zz;
}

// ---------------------------------------------------------------------------
__global__ void __launch_bounds__(256)
ln_kernel(const float* __restrict__ gamma, const float* __restrict__ beta,
          float* __restrict__ Y)
{
    __shared__ float sh[256], sh2[256];
    int row = blockIdx.x;
    int tid = threadIdx.x;
    const float* x = g_tmp + (size_t)row * DD;
    float s = 0.f, s2 = 0.f;
    for (int i = tid; i < DD; i += 256) {
        float v = x[i];
        s += v; s2 += v * v;
    }
    sh[tid] = s; sh2[tid] = s2;
    __syncthreads();
    for (int o = 128; o > 0; o >>= 1) {
        if (tid < o) { sh[tid] += sh[tid + o]; sh2[tid] += sh2[tid + o]; }
        __syncthreads();
    }
    float mean = sh[0] * (1.f / DD);
    float var  = sh2[0] * (1.f / DD) - mean * mean;
    float rstd = rsqrtf(var + 1e-6f);
    for (int i = tid; i < DD; i += 256) {
        float v = x[i];
        Y[(size_t)row * DD + i] = (v - mean) * rstd * gamma[i] + beta[i];
    }
}

// ---------------------------------------------------------------------------
extern "C" void kernel_launch(void* const* d_in, const int* in_sizes, int n_in,
                              void* d_out, int out_size)
{
    const float* q     = (const float*)d_in[0];
    const float* k     = (const float*)d_in[1];
    const float* v     = (const float*)d_in[2];
    const float* Wq    = (const float*)d_in[3];
    const float* Wk    = (const float*)d_in[4];
    const float* Wv    = (const float*)d_in[5];
    const float* Wfc   = (const float*)d_in[6];
    const float* gamma = (const float*)d_in[7];
    const float* beta  = (const float*)d_in[8];
    (void)in_sizes; (void)n_in;

    const long OUTE  = (long)MM * DD;
    const long ATTNE = (long)BB * HH * LL * LL;

    float* out_f = (float*)d_out;
    float* outm  = nullptr;
    float* attnp = nullptr;
    long osz = (long)out_size;
    if (osz >= OUTE + ATTNE) { outm = out_f; attnp = out_f + OUTE; }
    else if (osz == ATTNE)   { attnp = out_f; }
    else                     { outm = out_f; }

    cudaFuncSetAttribute(gemm3_kernel,
                         cudaFuncAttributeMaxDynamicSharedMemorySize, GEMM_SMEM);

    // Convert inputs to bf16 hi/lo
    conv_x_kernel<<<4096, 256>>>(q, 0, 0);
    conv_x_kernel<<<4096, 256>>>(k, 1, 0);
    conv_x_kernel<<<4096, 256>>>(v, 2, 0);
    dim3 gw(32, 32);
    conv_wt_kernel<<<gw, 256>>>(Wq, 0);
    conv_wt_kernel<<<gw, 256>>>(Wk, 1);
    conv_wt_kernel<<<gw, 256>>>(Wv, 2);
    conv_wt_kernel<<<gw, 256>>>(Wfc, 3);

    // Projections on tensor cores (3-term bf16, mma.sync)
    dim3 gg(DD / 64, MM / 128);   // (16, 32)
    gemm3_kernel<<<gg, 256, GEMM_SMEM>>>(0, 0, 0, nullptr);
    gemm3_kernel<<<gg, 256, GEMM_SMEM>>>(1, 1, 1, nullptr);
    gemm3_kernel<<<gg, 256, GEMM_SMEM>>>(2, 2, 2, nullptr);

    // Fused attention
    dim3 ga(LL / 64, HH, BB);
    float* attn_target = attnp ? attnp : (float*)d_out;
    attn_kernel<<<ga, 256, 49152>>>(attn_target, attnp ? 1 : 0);

    if (attnp) rescale_kernel<<<BB * HH * LL, 256>>>(attnp);

    if (outm) {
        conv_x_kernel<<<4096, 256>>>(nullptr, 0, 1);       // ctx -> slot 0
        gemm3_kernel<<<gg, 256, GEMM_SMEM>>>(0, 3, 3, q);  // fc + residual
        ln_kernel<<<MM, 256>>>(gamma, beta, outm);
    }
}

// round 16
// speedup vs baseline: 2.1824x; 1.5432x over previous
#include <cuda_runtime.h>
#include <cuda_bf16.h>
#include <cstdint>

#define BB 2
#define LL 2048
#define DD 1024
#define HH 16
#define MM (BB*LL)          // 4096

// ---------------- scratch ----------------
__device__ float g_ctx[(size_t)MM*DD];
__device__ float g_tmp[(size_t)MM*DD];
__device__ float g_rowinv[(size_t)BB*HH*LL];

__device__ __align__(16) __nv_bfloat16 g_ah[3][(size_t)MM*DD];
__device__ __align__(16) __nv_bfloat16 g_al[3][(size_t)MM*DD];
__device__ __align__(16) __nv_bfloat16 g_wh[4][(size_t)DD*DD];  // W^T [n][k]
__device__ __align__(16) __nv_bfloat16 g_wl[4][(size_t)DD*DD];

// projected heads, bf16 hi/lo, [b][h][l][64]; Q pre-scaled by 0.125
__device__ __align__(16) __nv_bfloat16 g_qhh[(size_t)BB*HH*LL*64];
__device__ __align__(16) __nv_bfloat16 g_qhl[(size_t)BB*HH*LL*64];
__device__ __align__(16) __nv_bfloat16 g_khh[(size_t)BB*HH*LL*64];
__device__ __align__(16) __nv_bfloat16 g_khl[(size_t)BB*HH*LL*64];
__device__ __align__(16) __nv_bfloat16 g_vhh[(size_t)BB*HH*LL*64];
__device__ __align__(16) __nv_bfloat16 g_vhl[(size_t)BB*HH*LL*64];

// ---------------- warp-MMA helpers ----------------
__device__ __forceinline__ uint32_t s2u(const void* p) {
    uint32_t a;
    asm("{ .reg .u64 t; cvta.to.shared.u64 t, %1; cvt.u32.u64 %0, t; }"
        : "=r"(a) : "l"(p));
    return a;
}
__device__ __forceinline__ void ldsm4(uint32_t* r, uint32_t a) {
    asm volatile("ldmatrix.sync.aligned.m8n8.x4.shared.b16 {%0,%1,%2,%3}, [%4];"
        : "=r"(r[0]), "=r"(r[1]), "=r"(r[2]), "=r"(r[3]) : "r"(a));
}
__device__ __forceinline__ void ldsm2(uint32_t* r, uint32_t a) {
    asm volatile("ldmatrix.sync.aligned.m8n8.x2.shared.b16 {%0,%1}, [%2];"
        : "=r"(r[0]), "=r"(r[1]) : "r"(a));
}
__device__ __forceinline__ void ldsm2t(uint32_t* r, uint32_t a) {
    asm volatile("ldmatrix.sync.aligned.m8n8.x2.trans.shared.b16 {%0,%1}, [%2];"
        : "=r"(r[0]), "=r"(r[1]) : "r"(a));
}
__device__ __forceinline__ void mma16816(float* d, const uint32_t* a, const uint32_t* b) {
    asm volatile(
        "mma.sync.aligned.m16n8k16.row.col.f32.bf16.bf16.f32 "
        "{%0,%1,%2,%3}, {%4,%5,%6,%7}, {%8,%9}, {%0,%1,%2,%3};"
        : "+f"(d[0]), "+f"(d[1]), "+f"(d[2]), "+f"(d[3])
        : "r"(a[0]), "r"(a[1]), "r"(a[2]), "r"(a[3]), "r"(b[0]), "r"(b[1]));
}
__device__ __forceinline__ uint32_t pack2(float a, float b, float* ra, float* rb) {
    __nv_bfloat16 h0 = __float2bfloat16(a), h1 = __float2bfloat16(b);
    *ra = a - __bfloat162float(h0);
    *rb = b - __bfloat162float(h1);
    return (uint32_t)__bfloat16_as_ushort(h0)
         | ((uint32_t)__bfloat16_as_ushort(h1) << 16);
}
__device__ __forceinline__ uint32_t pack2n(float a, float b) {
    __nv_bfloat16 h0 = __float2bfloat16(a), h1 = __float2bfloat16(b);
    return (uint32_t)__bfloat16_as_ushort(h0)
         | ((uint32_t)__bfloat16_as_ushort(h1) << 16);
}

// ---------------- conversion kernels ----------------
__global__ void __launch_bounds__(256)
conv_x_kernel(const float* __restrict__ X, int slot, int fromCtx)
{
    const float* src = fromCtx ? g_ctx : X;
    size_t i = ((size_t)blockIdx.x * 256 + threadIdx.x) * 4;
    float4 v = *(const float4*)(src + i);
    float l0, l1, l2, l3;
    uint2 H, L;
    H.x = pack2(v.x, v.y, &l0, &l1);
    H.y = pack2(v.z, v.w, &l2, &l3);
    L.x = pack2n(l0, l1);
    L.y = pack2n(l2, l3);
    *(uint2*)&g_ah[slot][i] = H;
    *(uint2*)&g_al[slot][i] = L;
}

__global__ void __launch_bounds__(256)
conv_wt_kernel(const float* __restrict__ W, int slot)
{
    __shared__ float t[32][33];
    int n0 = blockIdx.x * 32, k0 = blockIdx.y * 32;
    int tx = threadIdx.x & 31, ty = threadIdx.x >> 5;
    #pragma unroll
    for (int i = 0; i < 4; i++)
        t[ty + 8 * i][tx] = W[(size_t)(k0 + ty + 8 * i) * DD + n0 + tx];
    __syncthreads();
    #pragma unroll
    for (int i = 0; i < 4; i++) {
        float v = t[tx][ty + 8 * i];
        size_t o = (size_t)(n0 + ty + 8 * i) * DD + k0 + tx;
        __nv_bfloat16 h = __float2bfloat16(v);
        g_wh[slot][o] = h;
        g_wl[slot][o] = __float2bfloat16(v - __bfloat162float(h));
    }
}

// ---------------- 3-term bf16 GEMM via mma.sync ----------------
#define AST 144
#define SM_AH 0
#define SM_AL (128*AST)
#define SM_BH (2*128*AST)
#define SM_BL (2*128*AST + 64*AST)
#define GEMM_SMEM (2*128*AST + 2*64*AST)  // 55296

__global__ void __launch_bounds__(256)
gemm3_kernel(int aslot, int wslot, int mode, const float* __restrict__ R)
{
    extern __shared__ char smp[];
    uint32_t sb = s2u(smp);
    int tid = threadIdx.x, wid = tid >> 5, lane = tid & 31;
    int wm = wid >> 1, wn = wid & 1;
    int n0 = blockIdx.x * 64, m0 = blockIdx.y * 128;

    const __nv_bfloat16* Ah = g_ah[aslot];
    const __nv_bfloat16* Al = g_al[aslot];
    const __nv_bfloat16* Bh = g_wh[wslot];
    const __nv_bfloat16* Bl = g_wl[wslot];

    float acc[2][4][4];
    #pragma unroll
    for (int mt = 0; mt < 2; mt++)
        #pragma unroll
        for (int nt = 0; nt < 4; nt++)
            #pragma unroll
            for (int j = 0; j < 4; j++) acc[mt][nt][j] = 0.f;

    for (int kt = 0; kt < 16; kt++) {
        int k0 = kt * 64;
        __syncthreads();
        #pragma unroll
        for (int i = 0; i < 12; i++) {
            int idx = i * 256 + tid;
            if (idx < 1024) {
                int r = idx >> 3, c = idx & 7;
                *(uint4*)(smp + SM_AH + r * AST + c * 16) =
                    *(const uint4*)&Ah[(size_t)(m0 + r) * DD + k0 + c * 8];
            } else if (idx < 2048) {
                int j = idx - 1024; int r = j >> 3, c = j & 7;
                *(uint4*)(smp + SM_AL + r * AST + c * 16) =
                    *(const uint4*)&Al[(size_t)(m0 + r) * DD + k0 + c * 8];
            } else if (idx < 2560) {
                int j = idx - 2048; int r = j >> 3, c = j & 7;
                *(uint4*)(smp + SM_BH + r * AST + c * 16) =
                    *(const uint4*)&Bh[(size_t)(n0 + r) * DD + k0 + c * 8];
            } else {
                int j = idx - 2560; int r = j >> 3, c = j & 7;
                *(uint4*)(smp + SM_BL + r * AST + c * 16) =
                    *(const uint4*)&Bl[(size_t)(n0 + r) * DD + k0 + c * 8];
            }
        }
        __syncthreads();
        #pragma unroll
        for (int s = 0; s < 4; s++) {
            int ks = s * 16;
            uint32_t aH[2][4], aL[2][4], bH[4][2], bL[4][2];
            #pragma unroll
            for (int mt = 0; mt < 2; mt++) {
                uint32_t ra = sb + SM_AH + (wm * 32 + mt * 16 + (lane & 15)) * AST
                            + (ks + (lane >> 4) * 8) * 2;
                ldsm4(aH[mt], ra);
                ldsm4(aL[mt], ra + (SM_AL - SM_AH));
            }
            #pragma unroll
            for (int nt = 0; nt < 4; nt++) {
                uint32_t rb = sb + SM_BH + (wn * 32 + nt * 8 + (lane & 7)) * AST
                            + (ks + ((lane >> 3) & 1) * 8) * 2;
                ldsm2(bH[nt], rb);
                ldsm2(bL[nt], rb + (SM_BL - SM_BH));
            }
            #pragma unroll
            for (int mt = 0; mt < 2; mt++)
                #pragma unroll
                for (int nt = 0; nt < 4; nt++) {
                    mma16816(acc[mt][nt], aH[mt], bH[nt]);
                    mma16816(acc[mt][nt], aH[mt], bL[nt]);
                    mma16816(acc[mt][nt], aL[mt], bH[nt]);
                }
        }
    }
    int r0 = lane >> 2, c0 = (lane & 3) * 2;
    float scale = (mode == 0) ? 0.125f : 1.0f;
    #pragma unroll
    for (int mt = 0; mt < 2; mt++)
        #pragma unroll
        for (int nt = 0; nt < 4; nt++) {
            int cc = wn * 32 + nt * 8 + c0;
            #pragma unroll
            for (int half = 0; half < 2; half++) {
                int m = m0 + wm * 32 + mt * 16 + r0 + half * 8;
                float v0 = acc[mt][nt][half * 2 + 0];
                float v1 = acc[mt][nt][half * 2 + 1];
                if (mode < 3) {
                    __nv_bfloat16* Yh = (mode == 0) ? g_qhh : (mode == 1) ? g_khh : g_vhh;
                    __nv_bfloat16* Yl = (mode == 0) ? g_qhl : (mode == 1) ? g_khl : g_vhl;
                    v0 *= scale; v1 *= scale;
                    int b = m >> 11, l = m & 2047, h = n0 >> 6;
                    size_t ro = ((size_t)((b * HH) + h) * LL + l) * 64 + cc;
                    float l0, l1;
                    uint32_t ph = pack2(v0, v1, &l0, &l1);
                    *(uint32_t*)&Yh[ro] = ph;
                    *(uint32_t*)&Yl[ro] = pack2n(l0, l1);
                } else {
                    size_t off = (size_t)m * DD + n0 + cc;
                    float2 rr = *(const float2*)&R[off];
                    float2 dv = make_float2(v0 + rr.x, v1 + rr.y);
                    *(float2*)&g_tmp[off] = dv;
                }
            }
        }
}

// ---------------- tensor-core attention ----------------
// Per block: (qt, h, b). 8 warps; warp (wm 0-3, wn 0-1) owns 16 q-rows x 32 cols.
// QK^T 3-term -> S fp32 frags -> mask+exp -> attn gmem + P hi/lo smem ->
// PV 3-term (V via ldmatrix.trans) -> O frags; rowsum -> 1/sum; O/sum -> g_ctx.
#define T_QH 0
#define T_QL (64*AST)
#define T_KH (2*64*AST)
#define T_KL (3*64*AST)
#define T_VH (4*64*AST)
#define T_VL (5*64*AST)
#define T_PH (6*64*AST)
#define T_PL (7*64*AST)
#define T_RED (8*64*AST)           // 64*2 floats = 512 B
#define T_RS  (8*64*AST + 512)     // 64 floats = 256 B
#define ATTN_SMEM (8*64*AST + 768) // 74496

__global__ void __launch_bounds__(256, 1)
attn_mma_kernel(float* __restrict__ attn, int writeAttn)
{
    extern __shared__ char smp[];
    uint32_t sb = s2u(smp);
    float* red = (float*)(smp + T_RED);
    float* rs  = (float*)(smp + T_RS);

    int qt = blockIdx.x, h = blockIdx.y, b = blockIdx.z;
    int q0 = qt * 64;
    int tid = threadIdx.x, wid = tid >> 5, lane = tid & 31;
    int wm = wid >> 1, wn = wid & 1;
    int r0 = lane >> 2, c0 = (lane & 3) * 2;
    size_t bh = (size_t)(b * HH + h);
    size_t hb = bh * LL;           // element row base in head tensors

    // load Q hi/lo tile (64x64): 2 tiles x 512 u4 -> 4 u4/thread
    #pragma unroll
    for (int i = 0; i < 2; i++) {
        int f = i * 256 + tid;
        int r = f >> 3, c = f & 7;
        size_t go = (hb + q0 + r) * 64 + c * 8;
        *(uint4*)(smp + T_QH + r * AST + c * 16) = *(const uint4*)&g_qhh[go];
        *(uint4*)(smp + T_QL + r * AST + c * 16) = *(const uint4*)&g_qhl[go];
    }

    float O[4][4];
    #pragma unroll
    for (int nt = 0; nt < 4; nt++)
        #pragma unroll
        for (int j = 0; j < 4; j++) O[nt][j] = 0.f;
    float sums[2] = {0.f, 0.f};

    for (int kt = 0; kt <= qt; kt++) {
        __syncthreads();   // prev PV done with K/V/P; Q load done (1st iter)
        // load K,V hi/lo tiles: 4 tiles x 512 u4 -> 8 u4/thread
        #pragma unroll
        for (int i = 0; i < 2; i++) {
            int f = i * 256 + tid;
            int r = f >> 3, c = f & 7;
            size_t go = (hb + kt * 64 + r) * 64 + c * 8;
            *(uint4*)(smp + T_KH + r * AST + c * 16) = *(const uint4*)&g_khh[go];
            *(uint4*)(smp + T_KL + r * AST + c * 16) = *(const uint4*)&g_khl[go];
            *(uint4*)(smp + T_VH + r * AST + c * 16) = *(const uint4*)&g_vhh[go];
            *(uint4*)(smp + T_VL + r * AST + c * 16) = *(const uint4*)&g_vhl[go];
        }
        __syncthreads();

        // S = Q K^T (3-term over d=64)
        float S[4][4];
        #pragma unroll
        for (int nt = 0; nt < 4; nt++)
            #pragma unroll
            for (int j = 0; j < 4; j++) S[nt][j] = 0.f;
        #pragma unroll
        for (int s = 0; s < 4; s++) {
            int ks = s * 16;
            uint32_t aH[4], aL[4], bH[4][2], bL[4][2];
            uint32_t ra = sb + T_QH + (wm * 16 + (lane & 15)) * AST
                        + (ks + (lane >> 4) * 8) * 2;
            ldsm4(aH, ra);
            ldsm4(aL, ra + (T_QL - T_QH));
            #pragma unroll
            for (int nt = 0; nt < 4; nt++) {
                uint32_t rb = sb + T_KH + (wn * 32 + nt * 8 + (lane & 7)) * AST
                            + (ks + ((lane >> 3) & 1) * 8) * 2;
                ldsm2(bH[nt], rb);
                ldsm2(bL[nt], rb + (T_KL - T_KH));
            }
            #pragma unroll
            for (int nt = 0; nt < 4; nt++) {
                mma16816(S[nt], aH, bH[nt]);
                mma16816(S[nt], aH, bL[nt]);
                mma16816(S[nt], aL, bH[nt]);
            }
        }

        // mask + exp; write attn gmem; split hi/lo -> P smem; rowsum
        bool diag = (kt == qt);
        #pragma unroll
        for (int nt = 0; nt < 4; nt++) {
            int kloc = wn * 32 + nt * 8 + c0;
            int kg = kt * 64 + kloc;
            #pragma unroll
            for (int half = 0; half < 2; half++) {
                int qrow = wm * 16 + r0 + half * 8;
                int qg = q0 + qrow;
                float e0 = (!diag || kg     <= qg) ? __expf(S[nt][half * 2 + 0]) : 0.f;
                float e1 = (!diag || kg + 1 <= qg) ? __expf(S[nt][half * 2 + 1]) : 0.f;
                sums[half] += e0 + e1;
                if (writeAttn)
                    *(float2*)&attn[(hb + qg) * LL + kg] = make_float2(e0, e1);
                float l0, l1;
                uint32_t ph = pack2(e0, e1, &l0, &l1);
                *(uint32_t*)(smp + T_PH + qrow * AST + kloc * 2) = ph;
                *(uint32_t*)(smp + T_PL + qrow * AST + kloc * 2) = pack2n(l0, l1);
            }
        }
        __syncthreads();   // P complete for all warps

        // O += P V (3-term over k=64 of this tile)
        #pragma unroll
        for (int s = 0; s < 4; s++) {
            int ks = s * 16;
            uint32_t pH[4], pL[4], vH[4][2], vL[4][2];
            uint32_t ra = sb + T_PH + (wm * 16 + (lane & 15)) * AST
                        + (ks + (lane >> 4) * 8) * 2;
            ldsm4(pH, ra);
            ldsm4(pL, ra + (T_PL - T_PH));
            #pragma unroll
            for (int nt = 0; nt < 4; nt++) {
                // V row-major [k][dv]; trans-load gives col-major B frag
                uint32_t rb = sb + T_VH + (ks + (lane & 15)) * AST
                            + (wn * 32 + nt * 8) * 2;
                ldsm2t(vH[nt], rb);
                ldsm2t(vL[nt], rb + (T_VL - T_VH));
            }
            #pragma unroll
            for (int nt = 0; nt < 4; nt++) {
                mma16816(O[nt], pH, vH[nt]);
                mma16816(O[nt], pH, vL[nt]);
                mma16816(O[nt], pL, vH[nt]);
            }
        }
    }

    // rowsum reduction: quad shfl -> per-warp row sums over its 32 cols
    float s0 = sums[0], s1 = sums[1];
    s0 += __shfl_xor_sync(0xFFFFFFFFu, s0, 1);
    s0 += __shfl_xor_sync(0xFFFFFFFFu, s0, 2);
    s1 += __shfl_xor_sync(0xFFFFFFFFu, s1, 1);
    s1 += __shfl_xor_sync(0xFFFFFFFFu, s1, 2);
    __syncthreads();   // P/V smem no longer needed; red region aliases nothing
    if ((lane & 3) == 0) {
        red[(wm * 16 + r0) * 2 + wn]     = s0;
        red[(wm * 16 + r0 + 8) * 2 + wn] = s1;
    }
    __syncthreads();
    if (tid < 64) {
        float t = red[tid * 2] + red[tid * 2 + 1];
        float inv = 1.f / t;
        rs[tid] = inv;
        g_rowinv[hb + q0 + tid] = inv;
    }
    __syncthreads();

    // write O / rowsum -> g_ctx [b*L + q][h*64 + dv]
    #pragma unroll
    for (int nt = 0; nt < 4; nt++) {
        int cc = wn * 32 + nt * 8 + c0;
        #pragma unroll
        for (int half = 0; half < 2; half++) {
            int qrow = wm * 16 + r0 + half * 8;
            float inv = rs[qrow];
            size_t off = ((size_t)(b * LL + q0 + qrow)) * DD + h * 64 + cc;
            *(float2*)&g_ctx[off] = make_float2(O[nt][half * 2 + 0] * inv,
                                                O[nt][half * 2 + 1] * inv);
        }
    }
}

// ---------------------------------------------------------------------------
__global__ void __launch_bounds__(256)
rescale_kernel(float* __restrict__ attn)
{
    int r = blockIdx.x;
    int q = r & (LL - 1);
    float inv = g_rowinv[r];
    size_t base = (size_t)r * LL;
    int kend = q + 1;
    for (int k = threadIdx.x; k < kend; k += 256)
        attn[base + k] *= inv;
    int z0 = (kend + 3) & ~3;
    for (int k = kend + threadIdx.x; k < z0; k += 256)
        attn[base + k] = 0.f;
    float4 zz = make_float4(0.f, 0.f, 0.f, 0.f);
    for (int k = z0 + threadIdx.x * 4; k < LL; k += 256 * 4)
        *(float4*)&attn[base + k] = zz;
}

// ---------------------------------------------------------------------------
__global__ void __launch_bounds__(256)
ln_kernel(const float* __restrict__ gamma, const float* __restrict__ beta,
          float* __restrict__ Y)
{
    __shared__ float sh[256], sh2[256];
    int row = blockIdx.x;
    int tid = threadIdx.x;
    const float* x = g_tmp + (size_t)row * DD;
    float s = 0.f, s2 = 0.f;
    for (int i = tid; i < DD; i += 256) {
        float v = x[i];
        s += v; s2 += v * v;
    }
    sh[tid] = s; sh2[tid] = s2;
    __syncthreads();
    for (int o = 128; o > 0; o >>= 1) {
        if (tid < o) { sh[tid] += sh[tid + o]; sh2[tid] += sh2[tid + o]; }
        __syncthreads();
    }
    float mean = sh[0] * (1.f / DD);
    float var  = sh2[0] * (1.f / DD) - mean * mean;
    float rstd = rsqrtf(var + 1e-6f);
    for (int i = tid; i < DD; i += 256) {
        float v = x[i];
        Y[(size_t)row * DD + i] = (v - mean) * rstd * gamma[i] + beta[i];
    }
}

// ---------------------------------------------------------------------------
extern "C" void kernel_launch(void* const* d_in, const int* in_sizes, int n_in,
                              void* d_out, int out_size)
{
    const float* q     = (const float*)d_in[0];
    const float* k     = (const float*)d_in[1];
    const float* v     = (const float*)d_in[2];
    const float* Wq    = (const float*)d_in[3];
    const float* Wk    = (const float*)d_in[4];
    const float* Wv    = (const float*)d_in[5];
    const float* Wfc   = (const float*)d_in[6];
    const float* gamma = (const float*)d_in[7];
    const float* beta  = (const float*)d_in[8];
    (void)in_sizes; (void)n_in;

    const long OUTE  = (long)MM * DD;
    const long ATTNE = (long)BB * HH * LL * LL;

    float* out_f = (float*)d_out;
    float* outm  = nullptr;
    float* attnp = nullptr;
    long osz = (long)out_size;
    if (osz >= OUTE + ATTNE) { outm = out_f; attnp = out_f + OUTE; }
    else if (osz == ATTNE)   { attnp = out_f; }
    else                     { outm = out_f; }

    cudaFuncSetAttribute(gemm3_kernel,
                         cudaFuncAttributeMaxDynamicSharedMemorySize, GEMM_SMEM);
    cudaFuncSetAttribute(attn_mma_kernel,
                         cudaFuncAttributeMaxDynamicSharedMemorySize, ATTN_SMEM);

    // inputs -> bf16 hi/lo
    conv_x_kernel<<<4096, 256>>>(q, 0, 0);
    conv_x_kernel<<<4096, 256>>>(k, 1, 0);
    conv_x_kernel<<<4096, 256>>>(v, 2, 0);
    dim3 gw(32, 32);
    conv_wt_kernel<<<gw, 256>>>(Wq, 0);
    conv_wt_kernel<<<gw, 256>>>(Wk, 1);
    conv_wt_kernel<<<gw, 256>>>(Wv, 2);
    conv_wt_kernel<<<gw, 256>>>(Wfc, 3);

    // projections -> bf16 hi/lo heads (Q pre-scaled 0.125)
    dim3 gg(DD / 64, MM / 128);
    gemm3_kernel<<<gg, 256, GEMM_SMEM>>>(0, 0, 0, nullptr);
    gemm3_kernel<<<gg, 256, GEMM_SMEM>>>(1, 1, 1, nullptr);
    gemm3_kernel<<<gg, 256, GEMM_SMEM>>>(2, 2, 2, nullptr);

    // tensor-core attention
    dim3 ga(LL / 64, HH, BB);
    float* attn_target = attnp ? attnp : (float*)d_out;
    attn_mma_kernel<<<ga, 256, ATTN_SMEM>>>(attn_target, attnp ? 1 : 0);

    if (attnp) rescale_kernel<<<BB * HH * LL, 256>>>(attnp);

    if (outm) {
        conv_x_kernel<<<4096, 256>>>(nullptr, 0, 1);       // ctx -> slot 0
        gemm3_kernel<<<gg, 256, GEMM_SMEM>>>(0, 3, 3, q);  // fc + residual
        ln_kernel<<<MM, 256>>>(gamma, beta, outm);
    }
}

// round 17
// speedup vs baseline: 2.2499x; 1.0309x over previous
#include <cuda_runtime.h>
#include <cuda_bf16.h>
#include <cstdint>

#define BB 2
#define LL 2048
#define DD 1024
#define HH 16
#define MM (BB*LL)          // 4096

// ---------------- scratch ----------------
__device__ float g_ctx[(size_t)MM*DD];
__device__ float g_tmp[(size_t)MM*DD];
__device__ float g_rowinv[(size_t)BB*HH*LL];

__device__ __align__(16) __nv_bfloat16 g_ah[3][(size_t)MM*DD];
__device__ __align__(16) __nv_bfloat16 g_al[3][(size_t)MM*DD];
__device__ __align__(16) __nv_bfloat16 g_wh[4][(size_t)DD*DD];  // W^T [n][k]
__device__ __align__(16) __nv_bfloat16 g_wl[4][(size_t)DD*DD];

// projected heads, bf16 hi/lo, [b][h][l][64]; Q pre-scaled by 0.125
__device__ __align__(16) __nv_bfloat16 g_qhh[(size_t)BB*HH*LL*64];
__device__ __align__(16) __nv_bfloat16 g_qhl[(size_t)BB*HH*LL*64];
__device__ __align__(16) __nv_bfloat16 g_khh[(size_t)BB*HH*LL*64];
__device__ __align__(16) __nv_bfloat16 g_khl[(size_t)BB*HH*LL*64];
__device__ __align__(16) __nv_bfloat16 g_vhh[(size_t)BB*HH*LL*64];
__device__ __align__(16) __nv_bfloat16 g_vhl[(size_t)BB*HH*LL*64];

// ---------------- warp-MMA helpers ----------------
__device__ __forceinline__ uint32_t s2u(const void* p) {
    uint32_t a;
    asm("{ .reg .u64 t; cvta.to.shared.u64 t, %1; cvt.u32.u64 %0, t; }"
        : "=r"(a) : "l"(p));
    return a;
}
__device__ __forceinline__ void ldsm4(uint32_t* r, uint32_t a) {
    asm volatile("ldmatrix.sync.aligned.m8n8.x4.shared.b16 {%0,%1,%2,%3}, [%4];"
        : "=r"(r[0]), "=r"(r[1]), "=r"(r[2]), "=r"(r[3]) : "r"(a));
}
__device__ __forceinline__ void ldsm2(uint32_t* r, uint32_t a) {
    asm volatile("ldmatrix.sync.aligned.m8n8.x2.shared.b16 {%0,%1}, [%2];"
        : "=r"(r[0]), "=r"(r[1]) : "r"(a));
}
__device__ __forceinline__ void ldsm2t(uint32_t* r, uint32_t a) {
    asm volatile("ldmatrix.sync.aligned.m8n8.x2.trans.shared.b16 {%0,%1}, [%2];"
        : "=r"(r[0]), "=r"(r[1]) : "r"(a));
}
__device__ __forceinline__ void mma16816(float* d, const uint32_t* a, const uint32_t* b) {
    asm volatile(
        "mma.sync.aligned.m16n8k16.row.col.f32.bf16.bf16.f32 "
        "{%0,%1,%2,%3}, {%4,%5,%6,%7}, {%8,%9}, {%0,%1,%2,%3};"
        : "+f"(d[0]), "+f"(d[1]), "+f"(d[2]), "+f"(d[3])
        : "r"(a[0]), "r"(a[1]), "r"(a[2]), "r"(a[3]), "r"(b[0]), "r"(b[1]));
}
__device__ __forceinline__ void cpa16(uint32_t saddr, const void* g) {
    asm volatile("cp.async.cg.shared.global [%0], [%1], 16;"
        :: "r"(saddr), "l"(g));
}
__device__ __forceinline__ void cpa_commit() {
    asm volatile("cp.async.commit_group;");
}
template<int N> __device__ __forceinline__ void cpa_wait() {
    asm volatile("cp.async.wait_group %0;" :: "n"(N));
}
__device__ __forceinline__ uint32_t pack2(float a, float b, float* ra, float* rb) {
    __nv_bfloat16 h0 = __float2bfloat16(a), h1 = __float2bfloat16(b);
    *ra = a - __bfloat162float(h0);
    *rb = b - __bfloat162float(h1);
    return (uint32_t)__bfloat16_as_ushort(h0)
         | ((uint32_t)__bfloat16_as_ushort(h1) << 16);
}
__device__ __forceinline__ uint32_t pack2n(float a, float b) {
    __nv_bfloat16 h0 = __float2bfloat16(a), h1 = __float2bfloat16(b);
    return (uint32_t)__bfloat16_as_ushort(h0)
         | ((uint32_t)__bfloat16_as_ushort(h1) << 16);
}

// ---------------- conversion kernels ----------------
__global__ void __launch_bounds__(256)
conv_x_kernel(const float* __restrict__ X, int slot, int fromCtx)
{
    const float* src = fromCtx ? g_ctx : X;
    size_t i = ((size_t)blockIdx.x * 256 + threadIdx.x) * 4;
    float4 v = *(const float4*)(src + i);
    float l0, l1, l2, l3;
    uint2 H, L;
    H.x = pack2(v.x, v.y, &l0, &l1);
    H.y = pack2(v.z, v.w, &l2, &l3);
    L.x = pack2n(l0, l1);
    L.y = pack2n(l2, l3);
    *(uint2*)&g_ah[slot][i] = H;
    *(uint2*)&g_al[slot][i] = L;
}

__global__ void __launch_bounds__(256)
conv_wt_kernel(const float* __restrict__ W, int slot)
{
    __shared__ float t[32][33];
    int n0 = blockIdx.x * 32, k0 = blockIdx.y * 32;
    int tx = threadIdx.x & 31, ty = threadIdx.x >> 5;
    #pragma unroll
    for (int i = 0; i < 4; i++)
        t[ty + 8 * i][tx] = W[(size_t)(k0 + ty + 8 * i) * DD + n0 + tx];
    __syncthreads();
    #pragma unroll
    for (int i = 0; i < 4; i++) {
        float v = t[tx][ty + 8 * i];
        size_t o = (size_t)(n0 + ty + 8 * i) * DD + k0 + tx;
        __nv_bfloat16 h = __float2bfloat16(v);
        g_wh[slot][o] = h;
        g_wl[slot][o] = __float2bfloat16(v - __bfloat162float(h));
    }
}

// ---------------- 3-term bf16 GEMM via mma.sync, cp.async 2-stage ----------
#define AST 144
#define SM_AH 0
#define SM_AL (128*AST)
#define SM_BH (2*128*AST)
#define SM_BL (2*128*AST + 64*AST)
#define GEMM_STAGE (2*128*AST + 2*64*AST)   // 55296
#define GEMM_SMEM (2*GEMM_STAGE)            // 110592

__global__ void __launch_bounds__(256)
gemm3_kernel(int aslot, int wslot, int mode, const float* __restrict__ R)
{
    extern __shared__ char smp[];
    uint32_t sb = s2u(smp);
    int tid = threadIdx.x, wid = tid >> 5, lane = tid & 31;
    int wm = wid >> 1, wn = wid & 1;
    int n0 = blockIdx.x * 64, m0 = blockIdx.y * 128;

    const __nv_bfloat16* Ah = g_ah[aslot];
    const __nv_bfloat16* Al = g_al[aslot];
    const __nv_bfloat16* Bh = g_wh[wslot];
    const __nv_bfloat16* Bl = g_wl[wslot];

    // async tile loader into stage st for K-chunk kt
    auto load_tile = [&](int st, int kt) {
        uint32_t sbase = sb + st * GEMM_STAGE;
        int k0 = kt * 64;
        #pragma unroll
        for (int i = 0; i < 12; i++) {
            int idx = i * 256 + tid;
            if (idx < 1024) {
                int r = idx >> 3, c = idx & 7;
                cpa16(sbase + SM_AH + r * AST + c * 16,
                      &Ah[(size_t)(m0 + r) * DD + k0 + c * 8]);
            } else if (idx < 2048) {
                int j = idx - 1024; int r = j >> 3, c = j & 7;
                cpa16(sbase + SM_AL + r * AST + c * 16,
                      &Al[(size_t)(m0 + r) * DD + k0 + c * 8]);
            } else if (idx < 2560) {
                int j = idx - 2048; int r = j >> 3, c = j & 7;
                cpa16(sbase + SM_BH + r * AST + c * 16,
                      &Bh[(size_t)(n0 + r) * DD + k0 + c * 8]);
            } else {
                int j = idx - 2560; int r = j >> 3, c = j & 7;
                cpa16(sbase + SM_BL + r * AST + c * 16,
                      &Bl[(size_t)(n0 + r) * DD + k0 + c * 8]);
            }
        }
        cpa_commit();
    };

    float acc[2][4][4];
    #pragma unroll
    for (int mt = 0; mt < 2; mt++)
        #pragma unroll
        for (int nt = 0; nt < 4; nt++)
            #pragma unroll
            for (int j = 0; j < 4; j++) acc[mt][nt][j] = 0.f;

    load_tile(0, 0);   // prologue

    for (int kt = 0; kt < 16; kt++) {
        if (kt < 15) { load_tile((kt + 1) & 1, kt + 1); cpa_wait<1>(); }
        else         { cpa_wait<0>(); }
        __syncthreads();
        uint32_t stb = sb + (kt & 1) * GEMM_STAGE;
        #pragma unroll
        for (int s = 0; s < 4; s++) {
            int ks = s * 16;
            uint32_t aH[2][4], aL[2][4], bH[4][2], bL[4][2];
            #pragma unroll
            for (int mt = 0; mt < 2; mt++) {
                uint32_t ra = stb + SM_AH + (wm * 32 + mt * 16 + (lane & 15)) * AST
                            + (ks + (lane >> 4) * 8) * 2;
                ldsm4(aH[mt], ra);
                ldsm4(aL[mt], ra + (SM_AL - SM_AH));
            }
            #pragma unroll
            for (int nt = 0; nt < 4; nt++) {
                uint32_t rb = stb + SM_BH + (wn * 32 + nt * 8 + (lane & 7)) * AST
                            + (ks + ((lane >> 3) & 1) * 8) * 2;
                ldsm2(bH[nt], rb);
                ldsm2(bL[nt], rb + (SM_BL - SM_BH));
            }
            #pragma unroll
            for (int mt = 0; mt < 2; mt++)
                #pragma unroll
                for (int nt = 0; nt < 4; nt++) {
                    mma16816(acc[mt][nt], aH[mt], bH[nt]);
                    mma16816(acc[mt][nt], aH[mt], bL[nt]);
                    mma16816(acc[mt][nt], aL[mt], bH[nt]);
                }
        }
        __syncthreads();   // compute done before buffer reused by kt+2 load
    }

    int r0 = lane >> 2, c0 = (lane & 3) * 2;
    float scale = (mode == 0) ? 0.125f : 1.0f;
    #pragma unroll
    for (int mt = 0; mt < 2; mt++)
        #pragma unroll
        for (int nt = 0; nt < 4; nt++) {
            int cc = wn * 32 + nt * 8 + c0;
            #pragma unroll
            for (int half = 0; half < 2; half++) {
                int m = m0 + wm * 32 + mt * 16 + r0 + half * 8;
                float v0 = acc[mt][nt][half * 2 + 0];
                float v1 = acc[mt][nt][half * 2 + 1];
                if (mode < 3) {
                    __nv_bfloat16* Yh = (mode == 0) ? g_qhh : (mode == 1) ? g_khh : g_vhh;
                    __nv_bfloat16* Yl = (mode == 0) ? g_qhl : (mode == 1) ? g_khl : g_vhl;
                    v0 *= scale; v1 *= scale;
                    int b = m >> 11, l = m & 2047, h = n0 >> 6;
                    size_t ro = ((size_t)((b * HH) + h) * LL + l) * 64 + cc;
                    float l0, l1;
                    uint32_t ph = pack2(v0, v1, &l0, &l1);
                    *(uint32_t*)&Yh[ro] = ph;
                    *(uint32_t*)&Yl[ro] = pack2n(l0, l1);
                } else {
                    size_t off = (size_t)m * DD + n0 + cc;
                    float2 rr = *(const float2*)&R[off];
                    float2 dv = make_float2(v0 + rr.x, v1 + rr.y);
                    *(float2*)&g_tmp[off] = dv;
                }
            }
        }
}

// ---------------- tensor-core attention, cp.async 2-stage KV ----------------
#define A_QH 0
#define A_QL (64*AST)
#define A_KV(st) ((2 + (st)*4)*64*AST)   // per stage: KH,KL,VH,VL regions
#define A_PH (10*64*AST)
#define A_PL (11*64*AST)
#define A_RED (12*64*AST)                 // 512 B
#define A_RS  (12*64*AST + 512)           // 256 B
#define ATTN_SMEM (12*64*AST + 768)       // 111360

__global__ void __launch_bounds__(256, 1)
attn_mma_kernel(float* __restrict__ attn, int writeAttn)
{
    extern __shared__ char smp[];
    uint32_t sb = s2u(smp);
    float* red = (float*)(smp + A_RED);
    float* rs  = (float*)(smp + A_RS);

    int qt = blockIdx.x, h = blockIdx.y, b = blockIdx.z;
    int q0 = qt * 64;
    int tid = threadIdx.x, wid = tid >> 5, lane = tid & 31;
    int wm = wid >> 1, wn = wid & 1;
    int r0 = lane >> 2, c0 = (lane & 3) * 2;
    size_t bh = (size_t)(b * HH + h);
    size_t hb = bh * LL;

    auto load_kv = [&](int st, int kt) {
        uint32_t kvb = sb + A_KV(st);
        #pragma unroll
        for (int i = 0; i < 2; i++) {
            int f = i * 256 + tid;
            int r = f >> 3, c = f & 7;
            size_t go = (hb + kt * 64 + r) * 64 + c * 8;
            uint32_t bo = r * AST + c * 16;
            cpa16(kvb + 0 * 64 * AST + bo, &g_khh[go]);
            cpa16(kvb + 1 * 64 * AST + bo, &g_khl[go]);
            cpa16(kvb + 2 * 64 * AST + bo, &g_vhh[go]);
            cpa16(kvb + 3 * 64 * AST + bo, &g_vhl[go]);
        }
        cpa_commit();
    };

    // Q tile (plain stores; visible after first in-loop sync)
    #pragma unroll
    for (int i = 0; i < 2; i++) {
        int f = i * 256 + tid;
        int r = f >> 3, c = f & 7;
        size_t go = (hb + q0 + r) * 64 + c * 8;
        *(uint4*)(smp + A_QH + r * AST + c * 16) = *(const uint4*)&g_qhh[go];
        *(uint4*)(smp + A_QL + r * AST + c * 16) = *(const uint4*)&g_qhl[go];
    }

    float O[4][4];
    #pragma unroll
    for (int nt = 0; nt < 4; nt++)
        #pragma unroll
        for (int j = 0; j < 4; j++) O[nt][j] = 0.f;
    float sums[2] = {0.f, 0.f};

    load_kv(0, 0);   // prologue

    for (int kt = 0; kt <= qt; kt++) {
        if (kt < qt) { load_kv((kt + 1) & 1, kt + 1); cpa_wait<1>(); }
        else         { cpa_wait<0>(); }
        __syncthreads();
        uint32_t kvb = sb + A_KV(kt & 1);

        // S = Q K^T (3-term over d=64)
        float S[4][4];
        #pragma unroll
        for (int nt = 0; nt < 4; nt++)
            #pragma unroll
            for (int j = 0; j < 4; j++) S[nt][j] = 0.f;
        #pragma unroll
        for (int s = 0; s < 4; s++) {
            int ks = s * 16;
            uint32_t aH[4], aL[4], bH[4][2], bL[4][2];
            uint32_t ra = sb + A_QH + (wm * 16 + (lane & 15)) * AST
                        + (ks + (lane >> 4) * 8) * 2;
            ldsm4(aH, ra);
            ldsm4(aL, ra + (A_QL - A_QH));
            #pragma unroll
            for (int nt = 0; nt < 4; nt++) {
                uint32_t rb = kvb + (wn * 32 + nt * 8 + (lane & 7)) * AST
                            + (ks + ((lane >> 3) & 1) * 8) * 2;
                ldsm2(bH[nt], rb);
                ldsm2(bL[nt], rb + 64 * AST);
            }
            #pragma unroll
            for (int nt = 0; nt < 4; nt++) {
                mma16816(S[nt], aH, bH[nt]);
                mma16816(S[nt], aH, bL[nt]);
                mma16816(S[nt], aL, bH[nt]);
            }
        }

        // mask + exp; write attn gmem; split hi/lo -> P smem; rowsum
        bool diag = (kt == qt);
        #pragma unroll
        for (int nt = 0; nt < 4; nt++) {
            int kloc = wn * 32 + nt * 8 + c0;
            int kg = kt * 64 + kloc;
            #pragma unroll
            for (int half = 0; half < 2; half++) {
                int qrow = wm * 16 + r0 + half * 8;
                int qg = q0 + qrow;
                float e0 = (!diag || kg     <= qg) ? __expf(S[nt][half * 2 + 0]) : 0.f;
                float e1 = (!diag || kg + 1 <= qg) ? __expf(S[nt][half * 2 + 1]) : 0.f;
                sums[half] += e0 + e1;
                if (writeAttn)
                    *(float2*)&attn[(hb + qg) * LL + kg] = make_float2(e0, e1);
                float l0, l1;
                uint32_t ph = pack2(e0, e1, &l0, &l1);
                *(uint32_t*)(smp + A_PH + qrow * AST + kloc * 2) = ph;
                *(uint32_t*)(smp + A_PL + qrow * AST + kloc * 2) = pack2n(l0, l1);
            }
        }
        __syncthreads();   // P complete for all warps

        // O += P V (3-term over k=64 of this tile)
        #pragma unroll
        for (int s = 0; s < 4; s++) {
            int ks = s * 16;
            uint32_t pH[4], pL[4], vH[4][2], vL[4][2];
            uint32_t ra = sb + A_PH + (wm * 16 + (lane & 15)) * AST
                        + (ks + (lane >> 4) * 8) * 2;
            ldsm4(pH, ra);
            ldsm4(pL, ra + (A_PL - A_PH));
            #pragma unroll
            for (int nt = 0; nt < 4; nt++) {
                uint32_t rb = kvb + 2 * 64 * AST + (ks + (lane & 15)) * AST
                            + (wn * 32 + nt * 8) * 2;
                ldsm2t(vH[nt], rb);
                ldsm2t(vL[nt], rb + 64 * AST);
            }
            #pragma unroll
            for (int nt = 0; nt < 4; nt++) {
                mma16816(O[nt], pH, vH[nt]);
                mma16816(O[nt], pH, vL[nt]);
                mma16816(O[nt], pL, vH[nt]);
            }
        }
        __syncthreads();   // done reading KV/P before buffer reuse
    }

    // rowsum reduction
    float s0 = sums[0], s1 = sums[1];
    s0 += __shfl_xor_sync(0xFFFFFFFFu, s0, 1);
    s0 += __shfl_xor_sync(0xFFFFFFFFu, s0, 2);
    s1 += __shfl_xor_sync(0xFFFFFFFFu, s1, 1);
    s1 += __shfl_xor_sync(0xFFFFFFFFu, s1, 2);
    if ((lane & 3) == 0) {
        red[(wm * 16 + r0) * 2 + wn]     = s0;
        red[(wm * 16 + r0 + 8) * 2 + wn] = s1;
    }
    __syncthreads();
    if (tid < 64) {
        float t = red[tid * 2] + red[tid * 2 + 1];
        float inv = 1.f / t;
        rs[tid] = inv;
        g_rowinv[hb + q0 + tid] = inv;
    }
    __syncthreads();

    #pragma unroll
    for (int nt = 0; nt < 4; nt++) {
        int cc = wn * 32 + nt * 8 + c0;
        #pragma unroll
        for (int half = 0; half < 2; half++) {
            int qrow = wm * 16 + r0 + half * 8;
            float inv = rs[qrow];
            size_t off = ((size_t)(b * LL + q0 + qrow)) * DD + h * 64 + cc;
            *(float2*)&g_ctx[off] = make_float2(O[nt][half * 2 + 0] * inv,
                                                O[nt][half * 2 + 1] * inv);
        }
    }
}

// ---------------------------------------------------------------------------
__global__ void __launch_bounds__(256)
rescale_kernel(float* __restrict__ attn)
{
    int r = blockIdx.x;
    int q = r & (LL - 1);
    float inv = g_rowinv[r];
    size_t base = (size_t)r * LL;
    int kend = q + 1;
    for (int k = threadIdx.x; k < kend; k += 256)
        attn[base + k] *= inv;
    int z0 = (kend + 3) & ~3;
    for (int k = kend + threadIdx.x; k < z0; k += 256)
        attn[base + k] = 0.f;
    float4 zz = make_float4(0.f, 0.f, 0.f, 0.f);
    for (int k = z0 + threadIdx.x * 4; k < LL; k += 256 * 4)
        *(float4*)&attn[base + k] = zz;
}

// ---------------------------------------------------------------------------
__global__ void __launch_bounds__(256)
ln_kernel(const float* __restrict__ gamma, const float* __restrict__ beta,
          float* __restrict__ Y)
{
    __shared__ float sh[256], sh2[256];
    int row = blockIdx.x;
    int tid = threadIdx.x;
    const float* x = g_tmp + (size_t)row * DD;
    float s = 0.f, s2 = 0.f;
    for (int i = tid; i < DD; i += 256) {
        float v = x[i];
        s += v; s2 += v * v;
    }
    sh[tid] = s; sh2[tid] = s2;
    __syncthreads();
    for (int o = 128; o > 0; o >>= 1) {
        if (tid < o) { sh[tid] += sh[tid + o]; sh2[tid] += sh2[tid + o]; }
        __syncthreads();
    }
    float mean = sh[0] * (1.f / DD);
    float var  = sh2[0] * (1.f / DD) - mean * mean;
    float rstd = rsqrtf(var + 1e-6f);
    for (int i = tid; i < DD; i += 256) {
        float v = x[i];
        Y[(size_t)row * DD + i] = (v - mean) * rstd * gamma[i] + beta[i];
    }
}

// ---------------------------------------------------------------------------
extern "C" void kernel_launch(void* const* d_in, const int* in_sizes, int n_in,
                              void* d_out, int out_size)
{
    const float* q     = (const float*)d_in[0];
    const float* k     = (const float*)d_in[1];
    const float* v     = (const float*)d_in[2];
    const float* Wq    = (const float*)d_in[3];
    const float* Wk    = (const float*)d_in[4];
    const float* Wv    = (const float*)d_in[5];
    const float* Wfc   = (const float*)d_in[6];
    const float* gamma = (const float*)d_in[7];
    const float* beta  = (const float*)d_in[8];
    (void)in_sizes; (void)n_in;

    const long OUTE  = (long)MM * DD;
    const long ATTNE = (long)BB * HH * LL * LL;

    float* out_f = (float*)d_out;
    float* outm  = nullptr;
    float* attnp = nullptr;
    long osz = (long)out_size;
    if (osz >= OUTE + ATTNE) { outm = out_f; attnp = out_f + OUTE; }
    else if (osz == ATTNE)   { attnp = out_f; }
    else                     { outm = out_f; }

    cudaFuncSetAttribute(gemm3_kernel,
                         cudaFuncAttributeMaxDynamicSharedMemorySize, GEMM_SMEM);
    cudaFuncSetAttribute(attn_mma_kernel,
                         cudaFuncAttributeMaxDynamicSharedMemorySize, ATTN_SMEM);

    // inputs -> bf16 hi/lo
    conv_x_kernel<<<4096, 256>>>(q, 0, 0);
    conv_x_kernel<<<4096, 256>>>(k, 1, 0);
    conv_x_kernel<<<4096, 256>>>(v, 2, 0);
    dim3 gw(32, 32);
    conv_wt_kernel<<<gw, 256>>>(Wq, 0);
    conv_wt_kernel<<<gw, 256>>>(Wk, 1);
    conv_wt_kernel<<<gw, 256>>>(Wv, 2);
    conv_wt_kernel<<<gw, 256>>>(Wfc, 3);

    // projections -> bf16 hi/lo heads (Q pre-scaled 0.125)
    dim3 gg(DD / 64, MM / 128);
    gemm3_kernel<<<gg, 256, GEMM_SMEM>>>(0, 0, 0, nullptr);
    gemm3_kernel<<<gg, 256, GEMM_SMEM>>>(1, 1, 1, nullptr);
    gemm3_kernel<<<gg, 256, GEMM_SMEM>>>(2, 2, 2, nullptr);

    // tensor-core attention
    dim3 ga(LL / 64, HH, BB);
    float* attn_target = attnp ? attnp : (float*)d_out;
    attn_mma_kernel<<<ga, 256, ATTN_SMEM>>>(attn_target, attnp ? 1 : 0);

    if (attnp) rescale_kernel<<<BB * HH * LL, 256>>>(attnp);

    if (outm) {
        conv_x_kernel<<<4096, 256>>>(nullptr, 0, 1);       // ctx -> slot 0
        gemm3_kernel<<<gg, 256, GEMM_SMEM>>>(0, 3, 3, q);  // fc + residual
        ln_kernel<<<MM, 256>>>(gamma, beta, outm);
    }
}